// round 12
// baseline (speedup 1.0000x reference)
#include <cuda_runtime.h>
#include <cuda_bf16.h>
#include <cstdint>

#define VOCAB   50000
#define NCELLS  16384
#define NQUADS  4096                 // cell-quads: 4 cells, 32 int4 tokens
#define RQUADS  12500                // vocab row-quads (4 rows each)
#define GRID    296                  // 2 blocks/SM -> single wave
#define THREADS 512                  // 16 warps
#define GROUPS  8
#define BPG     37                   // 8 * 37 = 296
#define SLICE   6256                 // padded slice (16B-aligned bases)
#define SLICE4  (SLICE / 4)          // 1564 float4
#define SLICE_BYTES (SLICE * 4)      // 25024 B smem
#define MAXQ    7                    // cell-quads per warp in phase B
#define NWARPS  (GRID * 16)          // 4736 warps in phase A

__device__ __align__(16) float g_proj[GROUPS * SLICE];
__device__ unsigned g_bar;           // barrier counter (monotonic across replays)

__global__ void __launch_bounds__(THREADS, 2) fused_kernel(
    const int*   __restrict__ x,
    const float* __restrict__ E,
    const float* __restrict__ W,
    const float* __restrict__ bias,
    float*       __restrict__ out)
{
    extern __shared__ float s_slice[];   // 25 KB

    int tid  = threadIdx.x;
    int lane = tid & 31;
    int wid  = tid >> 5;                 // 0..15

    // zero out[] for the phase-B atomics (blocks 0..31 x 512 = 16384)
    if (blockIdx.x < 32)
        out[blockIdx.x * THREADS + tid] = 0.0f;

    // ================= Phase A: proj, champion geometry =================
    // grid-stride over row-quads; 4 rows/warp, 8 front-batched LDG.128/thread
    {
        const float4* __restrict__ e4 = reinterpret_cast<const float4*>(E);
        const float4* __restrict__ w4 = reinterpret_cast<const float4*>(W);
        float4 wa = w4[lane];
        float4 wb = w4[lane + 32];

        for (int q = blockIdx.x * 16 + wid; q < RQUADS; q += NWARPS) {
            int row0 = q * 4;
            float4 r0a = e4[(size_t)(row0 + 0) * 64 + lane];
            float4 r0b = e4[(size_t)(row0 + 0) * 64 + lane + 32];
            float4 r1a = e4[(size_t)(row0 + 1) * 64 + lane];
            float4 r1b = e4[(size_t)(row0 + 1) * 64 + lane + 32];
            float4 r2a = e4[(size_t)(row0 + 2) * 64 + lane];
            float4 r2b = e4[(size_t)(row0 + 2) * 64 + lane + 32];
            float4 r3a = e4[(size_t)(row0 + 3) * 64 + lane];
            float4 r3b = e4[(size_t)(row0 + 3) * 64 + lane + 32];

            float s0 = 0.f, s1 = 0.f, s2 = 0.f, s3 = 0.f;
            s0 = fmaf(r0a.x, wa.x, s0); s0 = fmaf(r0a.y, wa.y, s0);
            s0 = fmaf(r0a.z, wa.z, s0); s0 = fmaf(r0a.w, wa.w, s0);
            s0 = fmaf(r0b.x, wb.x, s0); s0 = fmaf(r0b.y, wb.y, s0);
            s0 = fmaf(r0b.z, wb.z, s0); s0 = fmaf(r0b.w, wb.w, s0);

            s1 = fmaf(r1a.x, wa.x, s1); s1 = fmaf(r1a.y, wa.y, s1);
            s1 = fmaf(r1a.z, wa.z, s1); s1 = fmaf(r1a.w, wa.w, s1);
            s1 = fmaf(r1b.x, wb.x, s1); s1 = fmaf(r1b.y, wb.y, s1);
            s1 = fmaf(r1b.z, wb.z, s1); s1 = fmaf(r1b.w, wb.w, s1);

            s2 = fmaf(r2a.x, wa.x, s2); s2 = fmaf(r2a.y, wa.y, s2);
            s2 = fmaf(r2a.z, wa.z, s2); s2 = fmaf(r2a.w, wa.w, s2);
            s2 = fmaf(r2b.x, wb.x, s2); s2 = fmaf(r2b.y, wb.y, s2);
            s2 = fmaf(r2b.z, wb.z, s2); s2 = fmaf(r2b.w, wb.w, s2);

            s3 = fmaf(r3a.x, wa.x, s3); s3 = fmaf(r3a.y, wa.y, s3);
            s3 = fmaf(r3a.z, wa.z, s3); s3 = fmaf(r3a.w, wa.w, s3);
            s3 = fmaf(r3b.x, wb.x, s3); s3 = fmaf(r3b.y, wb.y, s3);
            s3 = fmaf(r3b.z, wb.z, s3); s3 = fmaf(r3b.w, wb.w, s3);

            #pragma unroll
            for (int o = 16; o > 0; o >>= 1) {
                s0 += __shfl_xor_sync(0xFFFFFFFFu, s0, o);
                s1 += __shfl_xor_sync(0xFFFFFFFFu, s1, o);
                s2 += __shfl_xor_sync(0xFFFFFFFFu, s2, o);
                s3 += __shfl_xor_sync(0xFFFFFFFFu, s3, o);
            }
            if (lane == 0)
                reinterpret_cast<float4*>(g_proj)[q] =
                    make_float4(s0, s1, s2, s3);
        }
    }

    // ============ grid barrier (single wave: 296 blocks, 2/SM) ============
    __syncthreads();
    if (tid == 0) {
        unsigned old;
        asm volatile("atom.add.release.gpu.u32 %0, [%1], %2;"
                     : "=r"(old) : "l"(&g_bar), "r"(1u) : "memory");
        unsigned target = old - (old % (unsigned)GRID) + (unsigned)GRID;
        unsigned cur;
        do {
            asm volatile("ld.acquire.gpu.u32 %0, [%1];"
                         : "=r"(cur) : "l"(&g_bar) : "memory");
        } while (cur < target);
    }
    __syncthreads();

    // ============ Phase B: slice fill + gather + atomic accumulate ============
    int grp  = blockIdx.x / BPG;     // 0..7
    int j    = blockIdx.x % BPG;     // 0..36
    int base = grp * SLICE;

    {
        uint32_t sbase = (uint32_t)__cvta_generic_to_shared(s_slice);
        const float4* __restrict__ g4 =
            reinterpret_cast<const float4*>(g_proj) + grp * SLICE4;
        #pragma unroll 4
        for (int i = tid; i < SLICE4; i += THREADS) {
            asm volatile("cp.async.cg.shared.global [%0], [%1], 16;"
                         :: "r"(sbase + i * 16), "l"(g4 + i));
        }
        asm volatile("cp.async.commit_group;");
    }

    // prefetch x quads + bias while the fill is in flight
    const int4* __restrict__ x4 = reinterpret_cast<const int4*>(x);
    int4 tq[MAXQ];
    #pragma unroll
    for (int i = 0; i < MAXQ; ++i) {
        int q = j + BPG * (wid + 16 * i);
        if (q < NQUADS) tq[i] = x4[q * 32 + lane];
    }
    float bv = (grp == 0) ? bias[0] : 0.0f;

    asm volatile("cp.async.wait_group 0;" ::: "memory");
    __syncthreads();

    #pragma unroll
    for (int i = 0; i < MAXQ; ++i) {
        int q = j + BPG * (wid + 16 * i);
        if (q >= NQUADS) break;

        int4 t = tq[i];
        float s = 0.0f;
        unsigned i0 = (unsigned)(t.x - base);
        unsigned i1 = (unsigned)(t.y - base);
        unsigned i2 = (unsigned)(t.z - base);
        unsigned i3 = (unsigned)(t.w - base);
        if (i0 < (unsigned)SLICE) s += s_slice[i0];
        if (i1 < (unsigned)SLICE) s += s_slice[i1];
        if (i2 < (unsigned)SLICE) s += s_slice[i2];
        if (i3 < (unsigned)SLICE) s += s_slice[i3];

        s += __shfl_xor_sync(0xFFFFFFFFu, s, 4);
        s += __shfl_xor_sync(0xFFFFFFFFu, s, 2);
        s += __shfl_xor_sync(0xFFFFFFFFu, s, 1);

        if ((lane & 7) == 0)
            atomicAdd(&out[q * 4 + (lane >> 3)], s + bv);
    }
}

extern "C" void kernel_launch(void* const* d_in, const int* in_sizes, int n_in,
                              void* d_out, int out_size)
{
    const int*   x = (const int*)  d_in[0];
    const float* E = (const float*)d_in[1];
    const float* W = (const float*)d_in[2];
    const float* b = (const float*)d_in[3];
    float* out = (float*)d_out;

    fused_kernel<<<GRID, THREADS, SLICE_BYTES>>>(x, E, W, b, out);
}

// round 14
// speedup vs baseline: 1.0570x; 1.0570x over previous
#include <cuda_runtime.h>
#include <cuda_bf16.h>
#include <cstdint>

#define VOCAB   50000
#define NCELLS  16384
#define NQUADS  4096                 // cell-quads: 4 cells, 32 int4 tokens
#define TABLE_BYTES (VOCAB * 4)      // 200000 B

__device__ float g_proj[VOCAB];

// 32-byte (8-float) load with L2 evict_last pinning. Legal width on sm_103:
// ld.global.nc.L2::evict_last.v4.b64. Requires 32B-aligned address.
struct f8 { float4 a, b; };
__device__ __forceinline__ f8 ldg_el8(const void* p) {
    unsigned long long x0, x1, x2, x3;
    asm volatile("ld.global.nc.L2::evict_last.v4.b64 {%0,%1,%2,%3}, [%4];"
                 : "=l"(x0), "=l"(x1), "=l"(x2), "=l"(x3) : "l"(p));
    f8 r;
    r.a.x = __uint_as_float((unsigned)(x0));
    r.a.y = __uint_as_float((unsigned)(x0 >> 32));
    r.a.z = __uint_as_float((unsigned)(x1));
    r.a.w = __uint_as_float((unsigned)(x1 >> 32));
    r.b.x = __uint_as_float((unsigned)(x2));
    r.b.y = __uint_as_float((unsigned)(x2 >> 32));
    r.b.z = __uint_as_float((unsigned)(x3));
    r.b.w = __uint_as_float((unsigned)(x3 >> 32));
    return r;
}

__device__ __forceinline__ float dot8(const f8& v, const float4& w0, const float4& w1) {
    float s = 0.f;
    s = fmaf(v.a.x, w0.x, s); s = fmaf(v.a.y, w0.y, s);
    s = fmaf(v.a.z, w0.z, s); s = fmaf(v.a.w, w0.w, s);
    s = fmaf(v.b.x, w1.x, s); s = fmaf(v.b.y, w1.y, s);
    s = fmaf(v.b.z, w1.z, s); s = fmaf(v.b.w, w1.w, s);
    return s;
}

// ---------------------------------------------------------------------------
// Kernel 1: p[v] = dot(E[v,:], W). 4 rows/warp; each lane loads 32 B/row via
// v4.b64 evict_last (4 front-batched loads, 128 B/thread total). E stays
// pinned L2-resident across graph replays.
// ---------------------------------------------------------------------------
__global__ void __launch_bounds__(256) proj_kernel(
    const float* __restrict__ E,
    const float* __restrict__ W)
{
    int gwarp = (blockIdx.x * blockDim.x + threadIdx.x) >> 5;
    int lane  = threadIdx.x & 31;
    int row0  = gwarp * 4;
    if (row0 >= VOCAB) return;

    const char* __restrict__ Eb = reinterpret_cast<const char*>(E);
    const float4* __restrict__ w4 = reinterpret_cast<const float4*>(W);

    // W floats [lane*8, lane*8+8)
    float4 w0 = w4[lane * 2];
    float4 w1 = w4[lane * 2 + 1];

    size_t off = (size_t)row0 * 1024 + lane * 32;
    f8 r0 = ldg_el8(Eb + off);
    f8 r1 = ldg_el8(Eb + off + 1024);
    f8 r2 = ldg_el8(Eb + off + 2048);
    f8 r3 = ldg_el8(Eb + off + 3072);

    float s0 = dot8(r0, w0, w1);
    float s1 = dot8(r1, w0, w1);
    float s2 = dot8(r2, w0, w1);
    float s3 = dot8(r3, w0, w1);

    #pragma unroll
    for (int o = 16; o > 0; o >>= 1) {
        s0 += __shfl_xor_sync(0xFFFFFFFFu, s0, o);
        s1 += __shfl_xor_sync(0xFFFFFFFFu, s1, o);
        s2 += __shfl_xor_sync(0xFFFFFFFFu, s2, o);
        s3 += __shfl_xor_sync(0xFFFFFFFFu, s3, o);
    }
    if (lane == 0) {
        g_proj[row0 + 0] = s0;
        g_proj[row0 + 1] = s1;
        g_proj[row0 + 2] = s2;
        g_proj[row0 + 3] = s3;
    }
}

// ---------------------------------------------------------------------------
// Kernel 2 (R4 champion): 128 blocks x 1024 threads, 200 KB smem table,
// cp.async fill, x int4 prefetched under the fill, LDS gathers,
// 8-lane reduce, direct store. One cell-quad per warp.
// ---------------------------------------------------------------------------
__global__ void __launch_bounds__(1024) gather_kernel(
    const int*   __restrict__ x,
    const float* __restrict__ bias,
    float*       __restrict__ out)
{
    extern __shared__ float s_proj[];   // 200000 B

    uint32_t sbase = (uint32_t)__cvta_generic_to_shared(s_proj);
    const float4* __restrict__ g4 = reinterpret_cast<const float4*>(g_proj);
    for (int i = threadIdx.x; i < VOCAB / 4; i += 1024) {
        asm volatile("cp.async.cg.shared.global [%0], [%1], 16;"
                     :: "r"(sbase + i * 16), "l"(g4 + i));
    }
    asm volatile("cp.async.commit_group;");

    int wid  = threadIdx.x >> 5;
    int lane = threadIdx.x & 31;
    int gw   = blockIdx.x * 32 + wid;          // 0..4095 == NQUADS-1
    int4 t   = reinterpret_cast<const int4*>(x)[gw * 32 + lane];
    float bv = bias[0];

    asm volatile("cp.async.wait_group 0;" ::: "memory");
    __syncthreads();

    float s = s_proj[t.x] + s_proj[t.y] + s_proj[t.z] + s_proj[t.w];

    s += __shfl_xor_sync(0xFFFFFFFFu, s, 4);
    s += __shfl_xor_sync(0xFFFFFFFFu, s, 2);
    s += __shfl_xor_sync(0xFFFFFFFFu, s, 1);

    if ((lane & 7) == 0) out[gw * 4 + (lane >> 3)] = s + bv;
}

extern "C" void kernel_launch(void* const* d_in, const int* in_sizes, int n_in,
                              void* d_out, int out_size)
{
    const int*   x = (const int*)  d_in[0];
    const float* E = (const float*)d_in[1];
    const float* W = (const float*)d_in[2];
    const float* b = (const float*)d_in[3];
    float* out = (float*)d_out;

    static bool attr_done = false;
    if (!attr_done) {
        cudaFuncSetAttribute(gather_kernel,
                             cudaFuncAttributeMaxDynamicSharedMemorySize,
                             TABLE_BYTES);
        attr_done = true;
    }

    // proj: 12500 row-quads, 8 warps/block -> 1563 blocks
    proj_kernel<<<(VOCAB / 4 + 7) / 8, 256>>>(E, W);
    // gather: 128 blocks x 1024 threads, one cell-quad per warp
    gather_kernel<<<128, 1024, TABLE_BYTES>>>(x, b, out);
}